// round 4
// baseline (speedup 1.0000x reference)
#include <cuda_runtime.h>
#include <math.h>

#define N_TOK 4096
#define DIM   1024
#define HEADS 16
#define DHEAD 64
#define INNER 1024   // HEADS * DHEAD

// Scratch (device globals: allocation-free per harness rules)
__device__ float g_Q[N_TOK * INNER];
__device__ float g_K[N_TOK * INNER];
__device__ float g_V[N_TOK * INNER];
__device__ float g_A[N_TOK * INNER];

// ---------------------------------------------------------------------------
// SGEMM body: C[M x Nc] = A[M x K] @ B[K x Nc] (+ bias).
// 64x64 tile per block, BK=16, 256 threads, 4x4 register tile per thread.
// A staged k-major (transposed) in smem; B staged row-major, float4 reads.
// ---------------------------------------------------------------------------
__device__ __forceinline__ void gemm_body(const float* __restrict__ A,
                                          const float* __restrict__ B,
                                          const float* __restrict__ bias,
                                          float* __restrict__ C,
                                          int Nc, int K, bool with_bias)
{
    __shared__ float As[16][68];   // [k][m], padded
    __shared__ float Bs[16][64];   // [k][n]

    const int tid = threadIdx.x;
    const int tx = tid & 15;       // 0..15 -> n sub-tile
    const int ty = tid >> 4;       // 0..15 -> m sub-tile
    const int m0 = blockIdx.y * 64;
    const int n0 = blockIdx.x * 64;

    // load roles
    const int arow = tid >> 2;     // 0..63  (m within tile)
    const int akq  = tid & 3;      // 0..3   (k quarter)
    const int brow = tid >> 4;     // 0..15  (k within tile)
    const int bnq  = tid & 15;     // 0..15  (n quarter)

    const float* Aload = A + (size_t)(m0 + arow) * K + akq * 4;
    const float* Bload = B + (size_t)brow * Nc + n0 + bnq * 4;

    float acc[4][4] = {};

    for (int k0 = 0; k0 < K; k0 += 16) {
        float4 a4 = *(const float4*)(Aload + k0);
        float4 b4 = *(const float4*)(Bload + (size_t)k0 * Nc);
        As[akq * 4 + 0][arow] = a4.x;
        As[akq * 4 + 1][arow] = a4.y;
        As[akq * 4 + 2][arow] = a4.z;
        As[akq * 4 + 3][arow] = a4.w;
        *(float4*)&Bs[brow][bnq * 4] = b4;
        __syncthreads();

        #pragma unroll
        for (int k = 0; k < 16; k++) {
            float av[4];
            #pragma unroll
            for (int i = 0; i < 4; i++) av[i] = As[k][ty * 4 + i];
            float4 bv = *(float4*)&Bs[k][tx * 4];
            #pragma unroll
            for (int i = 0; i < 4; i++) {
                acc[i][0] += av[i] * bv.x;
                acc[i][1] += av[i] * bv.y;
                acc[i][2] += av[i] * bv.z;
                acc[i][3] += av[i] * bv.w;
            }
        }
        __syncthreads();
    }

    float4 bb = make_float4(0.f, 0.f, 0.f, 0.f);
    if (with_bias) bb = *(const float4*)&bias[n0 + tx * 4];

    #pragma unroll
    for (int i = 0; i < 4; i++) {
        const int m = m0 + ty * 4 + i;
        float4 o;
        o.x = acc[i][0] + bb.x;
        o.y = acc[i][1] + bb.y;
        o.z = acc[i][2] + bb.z;
        o.w = acc[i][3] + bb.w;
        *(float4*)&C[(size_t)m * Nc + n0 + tx * 4] = o;
    }
}

__global__ void __launch_bounds__(256) gemm_q_kernel(const float* __restrict__ x,
                                                     const float* __restrict__ W)
{ gemm_body(x, W, nullptr, g_Q, INNER, DIM, false); }

__global__ void __launch_bounds__(256) gemm_k_kernel(const float* __restrict__ x,
                                                     const float* __restrict__ W)
{ gemm_body(x, W, nullptr, g_K, INNER, DIM, false); }

__global__ void __launch_bounds__(256) gemm_v_kernel(const float* __restrict__ x,
                                                     const float* __restrict__ W)
{ gemm_body(x, W, nullptr, g_V, INNER, DIM, false); }

__global__ void __launch_bounds__(256) gemm_o_kernel(const float* __restrict__ Wo,
                                                     const float* __restrict__ bo,
                                                     float* __restrict__ out)
{ gemm_body(g_A, Wo, bo, out, DIM, INNER, true); }

// ---------------------------------------------------------------------------
// Flash attention: one block per (head, 64-query tile).
// 256 threads. Q staged once (k-major, scale*log2e folded in); K (k-major) and
// V (row-major) streamed in 64-key tiles. Online softmax in exp2 domain.
//
// Tile loads: each of 256 threads owns row lr = tid>>2 (0..63) and the
// 16-dim span [lq*16, lq*16+16) with lq = tid&3 — 4 float4s per thread,
// 4096 floats per tile (FIXED from R2: previously only 1024 were loaded).
//
// Dynamic smem: Qs 4096 + Ks 4096 + Vs 4096 + Ss 64*65 + 3*64 = 16640 floats.
// ---------------------------------------------------------------------------
#define FLASH_SMEM_FLOATS (4096 * 3 + 64 * 65 + 3 * 64)
#define FLASH_SMEM_BYTES  (FLASH_SMEM_FLOATS * 4)

__global__ void __launch_bounds__(256) flash_attn_kernel()
{
    extern __shared__ float sm[];
    float* Qs    = sm;               // [64][64]  Qs[d][r]
    float* Ks    = sm + 4096;        // [64][64]  Ks[d][c]
    float* Vs    = sm + 8192;        // [64][64]  Vs[c][d]
    float* Ss    = sm + 12288;       // [64][65]  padded
    float* row_m = sm + 12288 + 64 * 65;
    float* row_l = row_m + 64;
    float* row_a = row_l + 64;

    const int tid = threadIdx.x;
    const int tx = tid & 15;         // 0..15
    const int ty = tid >> 4;         // 0..15
    const int h  = blockIdx.x;
    const int q0 = blockIdx.y * 64;

    const float* Qg = g_Q + h * DHEAD;
    const float* Kg = g_K + h * DHEAD;
    const float* Vg = g_V + h * DHEAD;

    const int lr = tid >> 2;         // 0..63  row within tile
    const int lq = tid & 3;          // 0..3   16-dim span

    // Load Q tile transposed with scale*log2(e) folded in. Full 64 dims/row.
    {
        const float sc = 0.18033688011112042f;   // (1/sqrt(64)) * log2(e)
        const float* qrow = Qg + (size_t)(q0 + lr) * INNER;
        #pragma unroll
        for (int q = 0; q < 4; q++) {
            const int d0 = lq * 16 + q * 4;
            float4 q4 = *(const float4*)(qrow + d0);
            Qs[(d0 + 0) * 64 + lr] = q4.x * sc;
            Qs[(d0 + 1) * 64 + lr] = q4.y * sc;
            Qs[(d0 + 2) * 64 + lr] = q4.z * sc;
            Qs[(d0 + 3) * 64 + lr] = q4.w * sc;
        }
    }
    if (tid < 64) { row_m[tid] = -INFINITY; row_l[tid] = 0.f; }

    float o[4][4] = {};

    for (int kt = 0; kt < N_TOK; kt += 64) {
        __syncthreads();   // protect Ks/Vs/Ss (and first-iter Qs/stats)

        // Load K tile transposed, V tile direct. Full 64 dims/row.
        {
            const float* krow = Kg + (size_t)(kt + lr) * INNER;
            const float* vrow = Vg + (size_t)(kt + lr) * INNER;
            #pragma unroll
            for (int q = 0; q < 4; q++) {
                const int d0 = lq * 16 + q * 4;
                float4 k4 = *(const float4*)(krow + d0);
                Ks[(d0 + 0) * 64 + lr] = k4.x;
                Ks[(d0 + 1) * 64 + lr] = k4.y;
                Ks[(d0 + 2) * 64 + lr] = k4.z;
                Ks[(d0 + 3) * 64 + lr] = k4.w;
                float4 v4 = *(const float4*)(vrow + d0);
                *(float4*)&Vs[lr * 64 + d0] = v4;
            }
        }
        __syncthreads();

        // S = Q @ K^T (already in log2 domain)
        float s[4][4] = {};
        #pragma unroll 8
        for (int d = 0; d < 64; d++) {
            float qa[4];
            #pragma unroll
            for (int i = 0; i < 4; i++) qa[i] = Qs[d * 64 + ty * 4 + i];
            float4 kb = *(float4*)&Ks[d * 64 + tx * 4];
            #pragma unroll
            for (int i = 0; i < 4; i++) {
                s[i][0] += qa[i] * kb.x;
                s[i][1] += qa[i] * kb.y;
                s[i][2] += qa[i] * kb.z;
                s[i][3] += qa[i] * kb.w;
            }
        }
        #pragma unroll
        for (int i = 0; i < 4; i++)
            #pragma unroll
            for (int j = 0; j < 4; j++)
                Ss[(ty * 4 + i) * 65 + tx * 4 + j] = s[i][j];
        __syncthreads();

        // Online softmax: 4 threads per row, 16 cols each.
        {
            const int r = tid >> 2, q = tid & 3;
            float* row = Ss + r * 65 + q * 16;
            float pm = row[0];
            #pragma unroll
            for (int c = 1; c < 16; c++) pm = fmaxf(pm, row[c]);
            pm = fmaxf(pm, __shfl_xor_sync(0xffffffffu, pm, 1));
            pm = fmaxf(pm, __shfl_xor_sync(0xffffffffu, pm, 2));
            const float mold = row_m[r];
            const float mnew = fmaxf(mold, pm);
            float psum = 0.f;
            #pragma unroll
            for (int c = 0; c < 16; c++) {
                float p = exp2f(row[c] - mnew);
                row[c] = p;
                psum += p;
            }
            psum += __shfl_xor_sync(0xffffffffu, psum, 1);
            psum += __shfl_xor_sync(0xffffffffu, psum, 2);
            if (q == 0) {
                const float alpha = exp2f(mold - mnew);
                row_a[r] = alpha;
                row_m[r] = mnew;
                row_l[r] = row_l[r] * alpha + psum;
            }
        }
        __syncthreads();

        // O = O*alpha + P @ V
        float al[4];
        #pragma unroll
        for (int i = 0; i < 4; i++) al[i] = row_a[ty * 4 + i];
        #pragma unroll
        for (int i = 0; i < 4; i++)
            #pragma unroll
            for (int j = 0; j < 4; j++)
                o[i][j] *= al[i];

        #pragma unroll 8
        for (int c = 0; c < 64; c++) {
            float pa[4];
            #pragma unroll
            for (int i = 0; i < 4; i++) pa[i] = Ss[(ty * 4 + i) * 65 + c];
            float4 vb = *(float4*)&Vs[c * 64 + tx * 4];
            #pragma unroll
            for (int i = 0; i < 4; i++) {
                o[i][0] += pa[i] * vb.x;
                o[i][1] += pa[i] * vb.y;
                o[i][2] += pa[i] * vb.z;
                o[i][3] += pa[i] * vb.w;
            }
        }
    }

    // Normalize and write out: g_A[n][h*64 + d]
    #pragma unroll
    for (int i = 0; i < 4; i++) {
        const float inv_l = 1.f / row_l[ty * 4 + i];
        float4 w;
        w.x = o[i][0] * inv_l;
        w.y = o[i][1] * inv_l;
        w.z = o[i][2] * inv_l;
        w.w = o[i][3] * inv_l;
        *(float4*)&g_A[(size_t)(q0 + ty * 4 + i) * INNER + h * DHEAD + tx * 4] = w;
    }
}

// ---------------------------------------------------------------------------
extern "C" void kernel_launch(void* const* d_in, const int* in_sizes, int n_in,
                              void* d_out, int out_size)
{
    (void)in_sizes; (void)n_in; (void)out_size;
    const float* x  = (const float*)d_in[0];
    const float* Wq = (const float*)d_in[1];
    const float* Wk = (const float*)d_in[2];
    const float* Wv = (const float*)d_in[3];
    const float* Wo = (const float*)d_in[4];
    const float* bo = (const float*)d_in[5];
    float* out = (float*)d_out;

    // Non-stream API; deterministic and idempotent (capture-safe).
    cudaFuncSetAttribute(flash_attn_kernel,
                         cudaFuncAttributeMaxDynamicSharedMemorySize,
                         FLASH_SMEM_BYTES);

    const dim3 thr(256);
    const dim3 g_qkv(INNER / 64, N_TOK / 64);   // (16, 64)
    gemm_q_kernel<<<g_qkv, thr>>>(x, Wq);
    gemm_k_kernel<<<g_qkv, thr>>>(x, Wk);
    gemm_v_kernel<<<g_qkv, thr>>>(x, Wv);

    flash_attn_kernel<<<dim3(HEADS, N_TOK / 64), thr, FLASH_SMEM_BYTES>>>();

    gemm_o_kernel<<<dim3(DIM / 64, N_TOK / 64), thr>>>(Wo, bo, out);
}

// round 5
// speedup vs baseline: 1.0044x; 1.0044x over previous
#include <cuda_runtime.h>
#include <math.h>

#define N_TOK 4096
#define DIM   1024
#define HEADS 16
#define DHEAD 64
#define INNER 1024   // HEADS * DHEAD

// Scratch (device globals: allocation-free per harness rules)
__device__ float g_Q[N_TOK * INNER];
__device__ float g_K[N_TOK * INNER];
__device__ float g_V[N_TOK * INNER];
__device__ float g_A[N_TOK * INNER];

// ---------------------------------------------------------------------------
// SGEMM body: C[M x Nc] = A[M x K] @ B[K x Nc] (+ bias).
// 64x64 tile per block, BK=16, 256 threads, 4x4 register tile per thread.
// A staged k-major (transposed) in smem; B staged row-major, float4 reads.
// ---------------------------------------------------------------------------
__device__ __forceinline__ void gemm_body(const float* __restrict__ A,
                                          const float* __restrict__ B,
                                          const float* __restrict__ bias,
                                          float* __restrict__ C,
                                          int Nc, int K, bool with_bias)
{
    __shared__ float As[16][68];   // [k][m], padded
    __shared__ float Bs[16][64];   // [k][n]

    const int tid = threadIdx.x;
    const int tx = tid & 15;       // 0..15 -> n sub-tile
    const int ty = tid >> 4;       // 0..15 -> m sub-tile
    const int m0 = blockIdx.y * 64;
    const int n0 = blockIdx.x * 64;

    // load roles
    const int arow = tid >> 2;     // 0..63  (m within tile)
    const int akq  = tid & 3;      // 0..3   (k quarter)
    const int brow = tid >> 4;     // 0..15  (k within tile)
    const int bnq  = tid & 15;     // 0..15  (n quarter)

    const float* Aload = A + (size_t)(m0 + arow) * K + akq * 4;
    const float* Bload = B + (size_t)brow * Nc + n0 + bnq * 4;

    float acc[4][4] = {};

    for (int k0 = 0; k0 < K; k0 += 16) {
        float4 a4 = *(const float4*)(Aload + k0);
        float4 b4 = *(const float4*)(Bload + (size_t)k0 * Nc);
        As[akq * 4 + 0][arow] = a4.x;
        As[akq * 4 + 1][arow] = a4.y;
        As[akq * 4 + 2][arow] = a4.z;
        As[akq * 4 + 3][arow] = a4.w;
        *(float4*)&Bs[brow][bnq * 4] = b4;
        __syncthreads();

        #pragma unroll
        for (int k = 0; k < 16; k++) {
            float av[4];
            #pragma unroll
            for (int i = 0; i < 4; i++) av[i] = As[k][ty * 4 + i];
            float4 bv = *(float4*)&Bs[k][tx * 4];
            #pragma unroll
            for (int i = 0; i < 4; i++) {
                acc[i][0] += av[i] * bv.x;
                acc[i][1] += av[i] * bv.y;
                acc[i][2] += av[i] * bv.z;
                acc[i][3] += av[i] * bv.w;
            }
        }
        __syncthreads();
    }

    float4 bb = make_float4(0.f, 0.f, 0.f, 0.f);
    if (with_bias) bb = *(const float4*)&bias[n0 + tx * 4];

    #pragma unroll
    for (int i = 0; i < 4; i++) {
        const int m = m0 + ty * 4 + i;
        float4 o;
        o.x = acc[i][0] + bb.x;
        o.y = acc[i][1] + bb.y;
        o.z = acc[i][2] + bb.z;
        o.w = acc[i][3] + bb.w;
        *(float4*)&C[(size_t)m * Nc + n0 + tx * 4] = o;
    }
}

__global__ void __launch_bounds__(256) gemm_q_kernel(const float* __restrict__ x,
                                                     const float* __restrict__ W)
{ gemm_body(x, W, nullptr, g_Q, INNER, DIM, false); }

__global__ void __launch_bounds__(256) gemm_k_kernel(const float* __restrict__ x,
                                                     const float* __restrict__ W)
{ gemm_body(x, W, nullptr, g_K, INNER, DIM, false); }

__global__ void __launch_bounds__(256) gemm_v_kernel(const float* __restrict__ x,
                                                     const float* __restrict__ W)
{ gemm_body(x, W, nullptr, g_V, INNER, DIM, false); }

__global__ void __launch_bounds__(256) gemm_o_kernel(const float* __restrict__ Wo,
                                                     const float* __restrict__ bo,
                                                     float* __restrict__ out)
{ gemm_body(g_A, Wo, bo, out, DIM, INNER, true); }

// ---------------------------------------------------------------------------
// Flash attention: one block per (head, 64-query tile).
// 256 threads. Q staged once (k-major, scale*log2e folded in); K (k-major) and
// V (row-major) streamed in 64-key tiles. Online softmax in exp2 domain.
//
// Tile loads: each of 256 threads owns row lr = tid>>2 (0..63) and the
// 16-dim span [lq*16, lq*16+16) with lq = tid&3 — 4 float4s per thread,
// 4096 floats per tile (FIXED from R2: previously only 1024 were loaded).
//
// Dynamic smem: Qs 4096 + Ks 4096 + Vs 4096 + Ss 64*65 + 3*64 = 16640 floats.
// ---------------------------------------------------------------------------
#define FLASH_SMEM_FLOATS (4096 * 3 + 64 * 65 + 3 * 64)
#define FLASH_SMEM_BYTES  (FLASH_SMEM_FLOATS * 4)

__global__ void __launch_bounds__(256) flash_attn_kernel()
{
    extern __shared__ float sm[];
    float* Qs    = sm;               // [64][64]  Qs[d][r]
    float* Ks    = sm + 4096;        // [64][64]  Ks[d][c]
    float* Vs    = sm + 8192;        // [64][64]  Vs[c][d]
    float* Ss    = sm + 12288;       // [64][65]  padded
    float* row_m = sm + 12288 + 64 * 65;
    float* row_l = row_m + 64;
    float* row_a = row_l + 64;

    const int tid = threadIdx.x;
    const int tx = tid & 15;         // 0..15
    const int ty = tid >> 4;         // 0..15
    const int h  = blockIdx.x;
    const int q0 = blockIdx.y * 64;

    const float* Qg = g_Q + h * DHEAD;
    const float* Kg = g_K + h * DHEAD;
    const float* Vg = g_V + h * DHEAD;

    const int lr = tid >> 2;         // 0..63  row within tile
    const int lq = tid & 3;          // 0..3   16-dim span

    // Load Q tile transposed with scale*log2(e) folded in. Full 64 dims/row.
    {
        const float sc = 0.18033688011112042f;   // (1/sqrt(64)) * log2(e)
        const float* qrow = Qg + (size_t)(q0 + lr) * INNER;
        #pragma unroll
        for (int q = 0; q < 4; q++) {
            const int d0 = lq * 16 + q * 4;
            float4 q4 = *(const float4*)(qrow + d0);
            Qs[(d0 + 0) * 64 + lr] = q4.x * sc;
            Qs[(d0 + 1) * 64 + lr] = q4.y * sc;
            Qs[(d0 + 2) * 64 + lr] = q4.z * sc;
            Qs[(d0 + 3) * 64 + lr] = q4.w * sc;
        }
    }
    if (tid < 64) { row_m[tid] = -INFINITY; row_l[tid] = 0.f; }

    float o[4][4] = {};

    for (int kt = 0; kt < N_TOK; kt += 64) {
        __syncthreads();   // protect Ks/Vs/Ss (and first-iter Qs/stats)

        // Load K tile transposed, V tile direct. Full 64 dims/row.
        {
            const float* krow = Kg + (size_t)(kt + lr) * INNER;
            const float* vrow = Vg + (size_t)(kt + lr) * INNER;
            #pragma unroll
            for (int q = 0; q < 4; q++) {
                const int d0 = lq * 16 + q * 4;
                float4 k4 = *(const float4*)(krow + d0);
                Ks[(d0 + 0) * 64 + lr] = k4.x;
                Ks[(d0 + 1) * 64 + lr] = k4.y;
                Ks[(d0 + 2) * 64 + lr] = k4.z;
                Ks[(d0 + 3) * 64 + lr] = k4.w;
                float4 v4 = *(const float4*)(vrow + d0);
                *(float4*)&Vs[lr * 64 + d0] = v4;
            }
        }
        __syncthreads();

        // S = Q @ K^T (already in log2 domain)
        float s[4][4] = {};
        #pragma unroll 8
        for (int d = 0; d < 64; d++) {
            float qa[4];
            #pragma unroll
            for (int i = 0; i < 4; i++) qa[i] = Qs[d * 64 + ty * 4 + i];
            float4 kb = *(float4*)&Ks[d * 64 + tx * 4];
            #pragma unroll
            for (int i = 0; i < 4; i++) {
                s[i][0] += qa[i] * kb.x;
                s[i][1] += qa[i] * kb.y;
                s[i][2] += qa[i] * kb.z;
                s[i][3] += qa[i] * kb.w;
            }
        }
        #pragma unroll
        for (int i = 0; i < 4; i++)
            #pragma unroll
            for (int j = 0; j < 4; j++)
                Ss[(ty * 4 + i) * 65 + tx * 4 + j] = s[i][j];
        __syncthreads();

        // Online softmax: 4 threads per row, 16 cols each.
        {
            const int r = tid >> 2, q = tid & 3;
            float* row = Ss + r * 65 + q * 16;
            float pm = row[0];
            #pragma unroll
            for (int c = 1; c < 16; c++) pm = fmaxf(pm, row[c]);
            pm = fmaxf(pm, __shfl_xor_sync(0xffffffffu, pm, 1));
            pm = fmaxf(pm, __shfl_xor_sync(0xffffffffu, pm, 2));
            const float mold = row_m[r];
            const float mnew = fmaxf(mold, pm);
            float psum = 0.f;
            #pragma unroll
            for (int c = 0; c < 16; c++) {
                float p = exp2f(row[c] - mnew);
                row[c] = p;
                psum += p;
            }
            psum += __shfl_xor_sync(0xffffffffu, psum, 1);
            psum += __shfl_xor_sync(0xffffffffu, psum, 2);
            if (q == 0) {
                const float alpha = exp2f(mold - mnew);
                row_a[r] = alpha;
                row_m[r] = mnew;
                row_l[r] = row_l[r] * alpha + psum;
            }
        }
        __syncthreads();

        // O = O*alpha + P @ V
        float al[4];
        #pragma unroll
        for (int i = 0; i < 4; i++) al[i] = row_a[ty * 4 + i];
        #pragma unroll
        for (int i = 0; i < 4; i++)
            #pragma unroll
            for (int j = 0; j < 4; j++)
                o[i][j] *= al[i];

        #pragma unroll 8
        for (int c = 0; c < 64; c++) {
            float pa[4];
            #pragma unroll
            for (int i = 0; i < 4; i++) pa[i] = Ss[(ty * 4 + i) * 65 + c];
            float4 vb = *(float4*)&Vs[c * 64 + tx * 4];
            #pragma unroll
            for (int i = 0; i < 4; i++) {
                o[i][0] += pa[i] * vb.x;
                o[i][1] += pa[i] * vb.y;
                o[i][2] += pa[i] * vb.z;
                o[i][3] += pa[i] * vb.w;
            }
        }
    }

    // Normalize and write out: g_A[n][h*64 + d]
    #pragma unroll
    for (int i = 0; i < 4; i++) {
        const float inv_l = 1.f / row_l[ty * 4 + i];
        float4 w;
        w.x = o[i][0] * inv_l;
        w.y = o[i][1] * inv_l;
        w.z = o[i][2] * inv_l;
        w.w = o[i][3] * inv_l;
        *(float4*)&g_A[(size_t)(q0 + ty * 4 + i) * INNER + h * DHEAD + tx * 4] = w;
    }
}

// ---------------------------------------------------------------------------
extern "C" void kernel_launch(void* const* d_in, const int* in_sizes, int n_in,
                              void* d_out, int out_size)
{
    (void)in_sizes; (void)n_in; (void)out_size;
    const float* x  = (const float*)d_in[0];
    const float* Wq = (const float*)d_in[1];
    const float* Wk = (const float*)d_in[2];
    const float* Wv = (const float*)d_in[3];
    const float* Wo = (const float*)d_in[4];
    const float* bo = (const float*)d_in[5];
    float* out = (float*)d_out;

    // Non-stream API; deterministic and idempotent (capture-safe).
    cudaFuncSetAttribute(flash_attn_kernel,
                         cudaFuncAttributeMaxDynamicSharedMemorySize,
                         FLASH_SMEM_BYTES);

    const dim3 thr(256);
    const dim3 g_qkv(INNER / 64, N_TOK / 64);   // (16, 64)
    gemm_q_kernel<<<g_qkv, thr>>>(x, Wq);
    gemm_k_kernel<<<g_qkv, thr>>>(x, Wk);
    gemm_v_kernel<<<g_qkv, thr>>>(x, Wv);

    flash_attn_kernel<<<dim3(HEADS, N_TOK / 64), thr, FLASH_SMEM_BYTES>>>();

    gemm_o_kernel<<<dim3(DIM / 64, N_TOK / 64), thr>>>(Wo, bo, out);
}